// round 1
// baseline (speedup 1.0000x reference)
#include <cuda_runtime.h>
#include <math.h>

typedef unsigned long long ull;

// ---------------------------------------------------------------------------
// Scratch: conv kernel weights, tap-major  g_w[t][m(64)][n(144)], t=(kd*5+kh)*5+kw
// 0.1 conv scale folded in.
// ---------------------------------------------------------------------------
__device__ float g_w[125 * 64 * 144];

__device__ __forceinline__ float sus_f(float v) {
    return v > 0.f ? expf(-1.f / v) : 0.f;
}

// ---------------------------------------------------------------------------
// Builder: one thread per (tap, u, w) = 125*256 = 32000 threads
// ---------------------------------------------------------------------------
__global__ void build_weights_kernel(const float* __restrict__ wtp) {
    int id = blockIdx.x * blockDim.x + threadIdx.x;
    if (id >= 32000) return;
    int t  = id >> 8;
    int uw = id & 255;
    int u  = uw >> 4;
    int w  = uw & 15;

    int xi = t / 25, yi = (t / 5) % 5, zi = t % 5;
    float rx = -1.f + 0.5f * xi;
    float ry = -1.f + 0.5f * yi;
    float rz = -1.f + 0.5f * zi;
    float d  = sqrtf(rx * rx + ry * ry + rz * rz);

    const float EC = 1.14136f * expf(2.0f);
    float wv[7];
#pragma unroll
    for (int i = 0; i < 7; i++) wv[i] = 0.f;
#pragma unroll
    for (int r = 0; r < 5; r++) {
        float val  = (float)(r + 1) * (1.f / 6.f);
        float diff = (d - val) * 6.f;
        float e    = EC * sus_f(diff + 1.f) * sus_f(1.f - diff);
        if (e != 0.f) {
#pragma unroll
            for (int i = 0; i < 7; i++)
                wv[i] += e * wtp[r * 1792 + i * 256 + u * 16 + w];
        }
    }
    const float invS = 0.089442719099991587f;  // 1/5^1.5
#pragma unroll
    for (int i = 0; i < 7; i++) wv[i] *= invS;

    float n  = fmaxf(d, 1e-12f);
    float ux = rx / n, uy = ry / n, uz = rz / n;
    const float SQ3 = 1.7320508075688772f;
    const float SQ5 = 2.2360679774997896f;
    float sh1[3] = {SQ3 * ux, SQ3 * uy, SQ3 * uz};
    float sh2[5] = {SQ5 * SQ3 * ux * uz,
                    SQ5 * SQ3 * ux * uy,
                    SQ5 * (uy * uy - 0.5f * (ux * ux + uz * uz)),
                    SQ5 * SQ3 * uy * uz,
                    SQ5 * 0.5f * SQ3 * (uz * uz - ux * ux)};

    // Wigner 3j (1,1,2): C[i][j][k], i,j in 0..2, k in 0..4
    float C[3][3][5];
#pragma unroll
    for (int i = 0; i < 3; i++)
#pragma unroll
        for (int j = 0; j < 3; j++)
#pragma unroll
            for (int k = 0; k < 5; k++) C[i][j][k] = 0.f;
    {
        float s = sqrtf(2.f / 15.f);
        float h = 0.5f * sqrtf(3.f) * s;
        C[0][2][0] = h;  C[2][0][0] = h;
        C[0][1][1] = h;  C[1][0][1] = h;
        C[0][0][2] = -0.5f * s;  C[1][1][2] = s;  C[2][2][2] = -0.5f * s;
        C[1][2][3] = h;  C[2][1][3] = h;
        C[0][0][4] = -h; C[2][2][4] = h;
    }

    const float PW0 = 0.17677669529663687f;   // sqrt(1/32)
    const float PW1 = 0.25f;                  // sqrt(3/48)
    const float PW2 = 0.39528470752104744f;   // sqrt(5/32)
    const float F   = 0.1f;                   // conv output scale

    float* base = g_w + (size_t)t * 64 * 144;

    // m = u (scalar input rows)
    base[u * 144 + w] = F * PW0 * wv[0];
#pragma unroll
    for (int k = 0; k < 3; k++)
        base[u * 144 + 16 + 3 * w + k] = F * (PW1 / SQ3) * sh1[k] * wv[1];
#pragma unroll
    for (int k = 0; k < 5; k++)
        base[u * 144 + 64 + 5 * w + k] = F * (PW2 / SQ5) * sh2[k] * wv[2];

    // m = 16 + 3u + i (vector input rows)
#pragma unroll
    for (int i = 0; i < 3; i++) {
        int m = 16 + 3 * u + i;
        base[m * 144 + w] = F * (PW0 / SQ3) * sh1[i] * wv[4];
#pragma unroll
        for (int k = 0; k < 3; k++) {
            float t2 = 0.f;
#pragma unroll
            for (int j = 0; j < 5; j++) t2 += C[i][k][j] * sh2[j];  // C121[i,j,k]=C112[i,k,j]
            float v = (i == k ? (PW1 / SQ3) * wv[3] : 0.f) + PW1 * t2 * wv[6];
            base[m * 144 + 16 + 3 * w + k] = F * v;
        }
#pragma unroll
        for (int k = 0; k < 5; k++) {
            float t3 = 0.f;
#pragma unroll
            for (int j = 0; j < 3; j++) t3 += C[i][j][k] * sh1[j];
            base[m * 144 + 64 + 5 * w + k] = F * PW2 * t3 * wv[5];
        }
    }
}

// ---------------------------------------------------------------------------
// Packed f32x2 FMA helpers
// ---------------------------------------------------------------------------
__device__ __forceinline__ ull pack2(float x) {
    unsigned xi = __float_as_uint(x);
    ull p;
    asm("mov.b64 %0, {%1, %1};" : "=l"(p) : "r"(xi));
    return p;
}
__device__ __forceinline__ ull ffma2(ull a, ull b, ull c) {
    ull d;
    asm("fma.rn.f32x2 %0, %1, %2, %3;" : "=l"(d) : "l"(a), "l"(b), "l"(c));
    return d;
}

// ---------------------------------------------------------------------------
// Main conv kernel.
// Block: 4x4x4 spatial tile x all 144 co, 288 threads (16 m-threads x 18 co-threads).
// Smem: x halo tile [64ci][8][8][9] (147456 B) + weight double buffer 2x[64][144]
// ---------------------------------------------------------------------------
#define XS_FLOATS   (64 * 8 * 8 * 9)     // 36864
#define WS_FLOATS   (64 * 144)           // 9216
#define SMEM_FLOATS (XS_FLOATS + 2 * WS_FLOATS)
#define SMEM_BYTES  (SMEM_FLOATS * 4)    // 221184

__global__ void __launch_bounds__(288, 1)
conv_main_kernel(const float* __restrict__ x,
                 const float* __restrict__ wsc0,
                 const float* __restrict__ wsc1,
                 float* __restrict__ out) {
    extern __shared__ float sm[];
    float* xs  = sm;                       // [ci][dz][hy][9]
    float* wsA = sm + XS_FLOATS;
    float* wsB = wsA + WS_FLOATS;

    const int tid = threadIdx.x;
    const int b   = blockIdx.y;
    int bx = blockIdx.x;
    int td = bx / 100;
    int rm = bx % 100;
    int th = rm / 10;
    int tw = rm % 10;
    int d0 = td * 4, h0 = th * 4, w0 = tw * 4;

    const int tc = tid >> 4;   // 0..17 : co group (8 co each)
    const int tm = tid & 15;   // 0..15 : (ld,lh)
    const int ld = tm >> 2;
    const int lh = tm & 3;

    // ---- load input halo tile (zero padded) ----
    const float* xb = x + (size_t)b * 64 * 64000;
    for (int idx = tid; idx < 64 * 8 * 8 * 8; idx += 288) {
        int wx = idx & 7;
        int hy = (idx >> 3) & 7;
        int dz = (idx >> 6) & 7;
        int ci = idx >> 9;
        int dd = d0 + dz - 2;
        int hh = h0 + hy - 2;
        int ww = w0 + wx - 2;
        float v = 0.f;
        if ((unsigned)dd < 40u && (unsigned)hh < 40u && (unsigned)ww < 40u)
            v = xb[((ci * 40 + dd) * 40 + hh) * 40 + ww];
        xs[((ci * 8 + dz) * 8 + hy) * 9 + wx] = v;
    }

    // ---- stage tap-0 weights ----
    {
        const float4* gw4 = (const float4*)g_w;
        float4* wA4 = (float4*)wsA;
#pragma unroll
        for (int k = 0; k < 8; k++) {
            int j = tid + k * 288;          // 8*288 = 2304 = 9216/4 exactly
            wA4[j] = gw4[j];
        }
    }
    __syncthreads();

    ull acc[4][4];
#pragma unroll
    for (int i = 0; i < 4; i++)
#pragma unroll
        for (int j = 0; j < 4; j++) acc[i][j] = 0ull;

    float* cur = wsA;
    float* nxt = wsB;

    for (int t = 0; t < 125; t++) {
        float4 pre[8];
        if (t < 124) {
            const float4* gw4 = (const float4*)(g_w + (size_t)(t + 1) * WS_FLOATS);
#pragma unroll
            for (int k = 0; k < 8; k++) pre[k] = gw4[tid + k * 288];
        }

        int kd = t / 25, kh = (t / 5) % 5, kw = t % 5;
        const float* xsp = xs + ((ld + kd) * 8 + (lh + kh)) * 9 + kw;
        const ull*   wsp = (const ull*)cur;   // ull index: ci*72 + tc*4

#pragma unroll 4
        for (int ci = 0; ci < 64; ci++) {
            const float* xr = xsp + ci * 576;
            float x0 = xr[0], x1 = xr[1], x2 = xr[2], x3 = xr[3];
            ull p0 = pack2(x0), p1 = pack2(x1), p2 = pack2(x2), p3 = pack2(x3);
            const ull* wr = wsp + ci * 72 + tc * 4;
            ull w0p = wr[0], w1p = wr[1], w2p = wr[2], w3p = wr[3];
            acc[0][0] = ffma2(p0, w0p, acc[0][0]);
            acc[0][1] = ffma2(p0, w1p, acc[0][1]);
            acc[0][2] = ffma2(p0, w2p, acc[0][2]);
            acc[0][3] = ffma2(p0, w3p, acc[0][3]);
            acc[1][0] = ffma2(p1, w0p, acc[1][0]);
            acc[1][1] = ffma2(p1, w1p, acc[1][1]);
            acc[1][2] = ffma2(p1, w2p, acc[1][2]);
            acc[1][3] = ffma2(p1, w3p, acc[1][3]);
            acc[2][0] = ffma2(p2, w0p, acc[2][0]);
            acc[2][1] = ffma2(p2, w1p, acc[2][1]);
            acc[2][2] = ffma2(p2, w2p, acc[2][2]);
            acc[2][3] = ffma2(p2, w3p, acc[2][3]);
            acc[3][0] = ffma2(p3, w0p, acc[3][0]);
            acc[3][1] = ffma2(p3, w1p, acc[3][1]);
            acc[3][2] = ffma2(p3, w2p, acc[3][2]);
            acc[3][3] = ffma2(p3, w3p, acc[3][3]);
        }

        if (t < 124) {
            float4* n4 = (float4*)nxt;
#pragma unroll
            for (int k = 0; k < 8; k++) n4[tid + k * 288] = pre[k];
            __syncthreads();
            float* tmp = cur; cur = nxt; nxt = tmp;
        }
    }

    // ---- epilogue: add self-connection, write out ----
#pragma unroll
    for (int j = 0; j < 8; j++) {
        int co = tc * 8 + j;
        float4 v;
        float* vf = (float*)&v;
#pragma unroll
        for (int mi = 0; mi < 4; mi++) {
            ull a = acc[mi][j >> 1];
            unsigned bits = (j & 1) ? (unsigned)(a >> 32) : (unsigned)(a & 0xffffffffull);
            float val = __uint_as_float(bits);
            if (co < 16) {
                float s = 0.f;
#pragma unroll
                for (int u = 0; u < 16; u++)
                    s += __ldg(&wsc0[u * 16 + co]) *
                         xs[((u * 8 + ld + 2) * 8 + lh + 2) * 9 + 2 + mi];
                val += 0.25f * s;
            } else if (co < 64) {
                int wc = (co - 16) / 3;
                int ii = (co - 16) % 3;
                float s = 0.f;
#pragma unroll
                for (int u = 0; u < 16; u++)
                    s += __ldg(&wsc1[u * 16 + wc]) *
                         xs[(((16 + 3 * u + ii) * 8 + ld + 2) * 8 + lh + 2) * 9 + 2 + mi];
                val += 0.25f * s;
            }
            vf[mi] = val;
        }
        size_t oidx = ((((size_t)b * 144 + co) * 40 + (d0 + ld)) * 40 + (h0 + lh)) * 40 + w0;
        *(float4*)(out + oidx) = v;
    }
}

// ---------------------------------------------------------------------------
// Launch
// ---------------------------------------------------------------------------
extern "C" void kernel_launch(void* const* d_in, const int* in_sizes, int n_in,
                              void* d_out, int out_size) {
    const float* x    = (const float*)d_in[0];
    const float* wsc0 = (const float*)d_in[1];
    const float* wsc1 = (const float*)d_in[2];
    const float* wtp  = (const float*)d_in[3];
    float* out = (float*)d_out;

    build_weights_kernel<<<125, 256>>>(wtp);

    cudaFuncSetAttribute(conv_main_kernel,
                         cudaFuncAttributeMaxDynamicSharedMemorySize, SMEM_BYTES);
    dim3 grid(1000, 2);
    conv_main_kernel<<<grid, 288, SMEM_BYTES>>>(x, wsc0, wsc1, out);
}

// round 4
// speedup vs baseline: 6.9072x; 6.9072x over previous
#include <cuda_runtime.h>
#include <cuda_fp16.h>
#include <math.h>
#include <stdint.h>

// ===========================================================================
// Geometry: padded plane width 48 (w: 2+6 pad), height 44 rows (h: 2+2), dz 44
// n = ny*48 + wx, plane padded to 2304 rows. xp[b][dz][n][ci], ci contiguous.
// ===========================================================================
#define NPLANE 2304

__device__ __half g_xp[2ull * 44 * NPLANE * 64];
__device__ float  g_w [125 * 64 * 144];
__device__ __half g_wh[125 * 144 * 64];      // [t][co][ci], t=(kd*5+kh)*5+kw

__device__ __forceinline__ float sus_f(float v) {
    return v > 0.f ? expf(-1.f / v) : 0.f;
}

// ===========================================================================
// Builder: g_w[t][ci=64][co=144], 0.1 conv scale folded, self-connection
// folded into center tap t=62.
// ===========================================================================
__global__ void build_weights_kernel(const float* __restrict__ wtp,
                                     const float* __restrict__ wsc0,
                                     const float* __restrict__ wsc1) {
    int id = blockIdx.x * blockDim.x + threadIdx.x;
    if (id >= 32000) return;
    int t  = id >> 8;
    int uw = id & 255;
    int u  = uw >> 4;
    int w  = uw & 15;

    int xi = t / 25, yi = (t / 5) % 5, zi = t % 5;
    float rx = -1.f + 0.5f * xi;
    float ry = -1.f + 0.5f * yi;
    float rz = -1.f + 0.5f * zi;
    float d  = sqrtf(rx * rx + ry * ry + rz * rz);

    const float EC = 1.14136f * expf(2.0f);
    float wv[7];
#pragma unroll
    for (int i = 0; i < 7; i++) wv[i] = 0.f;
#pragma unroll
    for (int r = 0; r < 5; r++) {
        float val  = (float)(r + 1) * (1.f / 6.f);
        float diff = (d - val) * 6.f;
        float e    = EC * sus_f(diff + 1.f) * sus_f(1.f - diff);
        if (e != 0.f) {
#pragma unroll
            for (int i = 0; i < 7; i++)
                wv[i] += e * wtp[r * 1792 + i * 256 + u * 16 + w];
        }
    }
    const float invS = 0.089442719099991587f;  // 1/5^1.5
#pragma unroll
    for (int i = 0; i < 7; i++) wv[i] *= invS;

    float n  = fmaxf(d, 1e-12f);
    float ux = rx / n, uy = ry / n, uz = rz / n;
    const float SQ3 = 1.7320508075688772f;
    const float SQ5 = 2.2360679774997896f;
    float sh1[3] = {SQ3 * ux, SQ3 * uy, SQ3 * uz};
    float sh2[5] = {SQ5 * SQ3 * ux * uz,
                    SQ5 * SQ3 * ux * uy,
                    SQ5 * (uy * uy - 0.5f * (ux * ux + uz * uz)),
                    SQ5 * SQ3 * uy * uz,
                    SQ5 * 0.5f * SQ3 * (uz * uz - ux * ux)};

    float C[3][3][5];
#pragma unroll
    for (int i = 0; i < 3; i++)
#pragma unroll
        for (int j = 0; j < 3; j++)
#pragma unroll
            for (int k = 0; k < 5; k++) C[i][j][k] = 0.f;
    {
        float s = sqrtf(2.f / 15.f);
        float h = 0.5f * sqrtf(3.f) * s;
        C[0][2][0] = h;  C[2][0][0] = h;
        C[0][1][1] = h;  C[1][0][1] = h;
        C[0][0][2] = -0.5f * s;  C[1][1][2] = s;  C[2][2][2] = -0.5f * s;
        C[1][2][3] = h;  C[2][1][3] = h;
        C[0][0][4] = -h; C[2][2][4] = h;
    }

    const float PW0 = 0.17677669529663687f;
    const float PW1 = 0.25f;
    const float PW2 = 0.39528470752104744f;
    const float F   = 0.1f;

    float* base = g_w + (size_t)t * 64 * 144;

    base[u * 144 + w] = F * PW0 * wv[0];
#pragma unroll
    for (int k = 0; k < 3; k++)
        base[u * 144 + 16 + 3 * w + k] = F * (PW1 / SQ3) * sh1[k] * wv[1];
#pragma unroll
    for (int k = 0; k < 5; k++)
        base[u * 144 + 64 + 5 * w + k] = F * (PW2 / SQ5) * sh2[k] * wv[2];

#pragma unroll
    for (int i = 0; i < 3; i++) {
        int m = 16 + 3 * u + i;
        base[m * 144 + w] = F * (PW0 / SQ3) * sh1[i] * wv[4];
#pragma unroll
        for (int k = 0; k < 3; k++) {
            float t2 = 0.f;
#pragma unroll
            for (int j = 0; j < 5; j++) t2 += C[i][k][j] * sh2[j];
            float v = (i == k ? (PW1 / SQ3) * wv[3] : 0.f) + PW1 * t2 * wv[6];
            base[m * 144 + 16 + 3 * w + k] = F * v;
        }
#pragma unroll
        for (int k = 0; k < 5; k++) {
            float t3 = 0.f;
#pragma unroll
            for (int j = 0; j < 3; j++) t3 += C[i][j][k] * sh1[j];
            base[m * 144 + 64 + 5 * w + k] = F * PW2 * t3 * wv[5];
        }
    }

    if (t == 62) {  // fold self-connection into center tap
        base[u * 144 + w] += 0.25f * wsc0[u * 16 + w];
#pragma unroll
        for (int i = 0; i < 3; i++)
            base[(16 + 3 * u + i) * 144 + (16 + 3 * w + i)] += 0.25f * wsc1[u * 16 + w];
    }
}

// ===========================================================================
__global__ void zero_xp_kernel() {
    size_t n4 = 2ull * 44 * NPLANE * 64 * 2 / 16;   // float4 count
    float4 z = make_float4(0.f, 0.f, 0.f, 0.f);
    float4* a = (float4*)g_xp;
    for (size_t i = blockIdx.x * blockDim.x + threadIdx.x; i < n4;
         i += (size_t)gridDim.x * blockDim.x)
        a[i] = z;
}

// grid (ny=44, dz=44, b=2), 256 threads: transpose ci innermost, fp32->fp16
__global__ void fill_xp_kernel(const float* __restrict__ x) {
    int ny = blockIdx.x, dz = blockIdx.y, b = blockIdx.z;
    if (dz < 2 || dz >= 42 || ny < 2 || ny >= 42) return;
    __shared__ float sm[40 * 65];
    int tid = threadIdx.x;
    int d = dz - 2, h = ny - 2;
    for (int i = tid; i < 64 * 40; i += 256) {
        int ci = i / 40, w = i % 40;
        sm[w * 65 + ci] = x[((size_t)(b * 64 + ci) * 40 + d) * 1600 + h * 40 + w];
    }
    __syncthreads();
    size_t rowbase = ((size_t)(b * 44 + dz) * NPLANE + ny * 48) * 64;
    for (int j = tid; j < 40 * 64; j += 256) {
        int w = j / 64, ci = j % 64;
        g_xp[rowbase + (size_t)(w + 2) * 64 + ci] = __float2half(sm[w * 65 + ci]);
    }
}

// g_w [t][ci][co] fp32 -> g_wh [t][co][ci] fp16
__global__ void wh_convert_kernel() {
    int id = blockIdx.x * blockDim.x + threadIdx.x;
    if (id >= 125 * 144) return;
    int t = id / 144, co = id % 144;
    size_t o = ((size_t)t * 144 + co) * 64;
#pragma unroll 4
    for (int ci = 0; ci < 64; ci++)
        g_wh[o + ci] = __float2half(g_w[((size_t)t * 64 + ci) * 144 + co]);
}

// ===========================================================================
// Main conv kernel: implicit GEMM on mma.sync (HMMA), fp16 single pass.
// Block: 256 voxels x 144 co. 8 warps: warp tile 64x72 (mw=wid&3, nw=wid>>2).
// SMEM rows stride 144B (9x16B, odd -> conflict-free ldmatrix).
// ===========================================================================
#define A_ROWS 456
#define SM_A   0
#define SM_B0  (A_ROWS * 144)              // 65664
#define SM_B1  (SM_B0 + 144 * 144)         // 86400
#define SMEM_TOTAL (SM_B1 + 144 * 144)     // 107136

__device__ __forceinline__ uint32_t smem_u32(const void* p) {
    uint32_t a;
    asm("{ .reg .u64 t; cvta.to.shared.u64 t, %1; cvt.u32.u64 %0, t; }" : "=r"(a) : "l"(p));
    return a;
}
__device__ __forceinline__ void cpa16(uint32_t dst, const void* src) {
    asm volatile("cp.async.cg.shared.global [%0], [%1], 16;" :: "r"(dst), "l"(src));
}
__device__ __forceinline__ void cpa_commit() {
    asm volatile("cp.async.commit_group;" ::: "memory");
}
__device__ __forceinline__ void cpa_wait0() {
    asm volatile("cp.async.wait_group 0;" ::: "memory");
}
__device__ __forceinline__ void ldsm4(uint32_t* r, uint32_t addr) {
    asm volatile("ldmatrix.sync.aligned.m8n8.x4.shared.b16 {%0,%1,%2,%3}, [%4];"
                 : "=r"(r[0]), "=r"(r[1]), "=r"(r[2]), "=r"(r[3]) : "r"(addr));
}
__device__ __forceinline__ void ldsm2(uint32_t* r, uint32_t addr) {
    asm volatile("ldmatrix.sync.aligned.m8n8.x2.shared.b16 {%0,%1}, [%2];"
                 : "=r"(r[0]), "=r"(r[1]) : "r"(addr));
}
__device__ __forceinline__ void mma16816(float* d, const uint32_t* a, const uint32_t* bq) {
    asm volatile(
        "mma.sync.aligned.m16n8k16.row.col.f32.f16.f16.f32 "
        "{%0,%1,%2,%3}, {%4,%5,%6,%7}, {%8,%9}, {%0,%1,%2,%3};"
        : "+f"(d[0]), "+f"(d[1]), "+f"(d[2]), "+f"(d[3])
        : "r"(a[0]), "r"(a[1]), "r"(a[2]), "r"(a[3]), "r"(bq[0]), "r"(bq[1]));
}

__global__ void __launch_bounds__(256, 1)
conv_mma_kernel(float* __restrict__ out) {
    extern __shared__ char smem[];
    uint32_t sb = smem_u32(smem);
    const int tid  = threadIdx.x;
    const int lane = tid & 31;
    const int wid  = tid >> 5;
    const int mw   = wid & 3;     // M quarter (64 voxels)
    const int nw   = wid >> 2;    // N half (72 co)

    const int tileIdx = blockIdx.x;
    const int d = blockIdx.y;
    const int b = blockIdx.z;
    const int n0 = (tileIdx < 7) ? tileIdx * 256 : 1664;

    // ---- staging helpers ----
    auto stageA = [&](int g) {
        int kd = g / 5, kw = g % 5;
        const __half* src0 = g_xp + ((size_t)(b * 44 + d + kd) * NPLANE + n0 + kw) * 64;
        for (int i = tid; i < A_ROWS * 8; i += 256) {
            int r = i >> 3, c = i & 7;
            cpa16(sb + SM_A + r * 144 + c * 16, src0 + (size_t)r * 64 + c * 8);
        }
    };
    // loop index t = (kd*5 + kw)*5 + kh  ->  weight tap tw = (kd*5 + kh)*5 + kw
    auto stageB = [&](int t, uint32_t base) {
        int g = t / 5, kh = t % 5;
        int kd = g / 5, kw = g % 5;
        int tw = (kd * 5 + kh) * 5 + kw;
        const __half* src0 = g_wh + (size_t)tw * 144 * 64;
        for (int i = tid; i < 144 * 8; i += 256) {
            int r = i >> 3, c = i & 7;
            cpa16(base + r * 144 + c * 16, src0 + (size_t)r * 64 + c * 8);
        }
    };

    stageA(0);
    stageB(0, sb + SM_B0);
    cpa_commit();
    cpa_wait0();
    __syncthreads();

    float acc[4][9][4];
#pragma unroll
    for (int mt = 0; mt < 4; mt++)
#pragma unroll
        for (int nt = 0; nt < 9; nt++)
#pragma unroll
            for (int q = 0; q < 4; q++) acc[mt][nt][q] = 0.f;

    // lane-invariant parts of ldmatrix addresses
    const uint32_t aLane = sb + SM_A + (mw * 64 + (lane & 15)) * 144 + (lane >> 4) * 16;
    const uint32_t bOff4 = (uint32_t)((nw * 72 + ((lane >> 4) << 3) + (lane & 7)) * 144 +
                                      ((lane >> 3) & 1) * 16);
    const uint32_t bOff2 = (uint32_t)((nw * 72 + 64 + (lane & 7)) * 144 +
                                      ((lane >> 3) & 1) * 16);

    for (int t = 0; t < 125; t++) {
        int j = t % 5;
        if (t < 124) {
            stageB(t + 1, sb + (((t + 1) & 1) ? SM_B1 : SM_B0));
            cpa_commit();
        }

        uint32_t aTap  = aLane + (uint32_t)(j * 48 * 144);
        uint32_t bBase = sb + ((t & 1) ? SM_B1 : SM_B0);

#pragma unroll 1
        for (int ks = 0; ks < 4; ks++) {
            uint32_t a[4][4];
#pragma unroll
            for (int mt = 0; mt < 4; mt++)
                ldsm4(a[mt], aTap + mt * (16 * 144) + ks * 32);

            uint32_t bf[9][2];
#pragma unroll
            for (int nt = 0; nt < 4; nt++) {
                uint32_t r4[4];
                ldsm4(r4, bBase + bOff4 + nt * (16 * 144) + ks * 32);
                bf[2 * nt][0] = r4[0]; bf[2 * nt][1] = r4[1];
                bf[2 * nt + 1][0] = r4[2]; bf[2 * nt + 1][1] = r4[3];
            }
            ldsm2(bf[8], bBase + bOff2 + ks * 32);

#pragma unroll
            for (int mt = 0; mt < 4; mt++)
#pragma unroll
                for (int nt = 0; nt < 9; nt++)
                    mma16816(acc[mt][nt], a[mt], bf[nt]);
        }

        cpa_wait0();
        __syncthreads();
        if (j == 4 && t < 124) {
            stageA((t + 1) / 5);
            cpa_commit();
            cpa_wait0();
            __syncthreads();
        }
    }

    // ---- epilogue ----
    const size_t ob = (size_t)b * 144 * 64000 + (size_t)d * 1600;
#pragma unroll
    for (int mt = 0; mt < 4; mt++) {
        int v0 = n0 + mw * 64 + mt * 16 + (lane >> 2);
        int v1 = v0 + 8;
        int h0 = v0 / 48, w0 = v0 % 48;
        int h1 = v1 / 48, w1 = v1 % 48;
        bool ok0 = (w0 < 40) && (v0 < 1920);
        bool ok1 = (w1 < 40) && (v1 < 1920);
        size_t o0 = ob + h0 * 40 + w0;
        size_t o1 = ob + h1 * 40 + w1;
#pragma unroll
        for (int nt = 0; nt < 9; nt++) {
            int co = nw * 72 + nt * 8 + (lane & 3) * 2;
            if (ok0) {
                out[o0 + (size_t)co * 64000]       = acc[mt][nt][0];
                out[o0 + (size_t)(co + 1) * 64000] = acc[mt][nt][1];
            }
            if (ok1) {
                out[o1 + (size_t)co * 64000]       = acc[mt][nt][2];
                out[o1 + (size_t)(co + 1) * 64000] = acc[mt][nt][3];
            }
        }
    }
}

// ===========================================================================
extern "C" void kernel_launch(void* const* d_in, const int* in_sizes, int n_in,
                              void* d_out, int out_size) {
    const float* x    = (const float*)d_in[0];
    const float* wsc0 = (const float*)d_in[1];
    const float* wsc1 = (const float*)d_in[2];
    const float* wtp  = (const float*)d_in[3];
    float* out = (float*)d_out;

    zero_xp_kernel<<<2048, 256>>>();
    fill_xp_kernel<<<dim3(44, 44, 2), 256>>>(x);
    build_weights_kernel<<<125, 256>>>(wtp, wsc0, wsc1);
    wh_convert_kernel<<<(125 * 144 + 255) / 256, 256>>>();

    cudaFuncSetAttribute(conv_mma_kernel,
                         cudaFuncAttributeMaxDynamicSharedMemorySize, SMEM_TOTAL);
    conv_mma_kernel<<<dim3(8, 40, 2), 256, SMEM_TOTAL>>>(out);
}

// round 5
// speedup vs baseline: 9.7164x; 1.4067x over previous
#include <cuda_runtime.h>
#include <cuda_fp16.h>
#include <math.h>
#include <stdint.h>

// ===========================================================================
// Geometry: plane width 44 (w pad 2+2), height 44 rows (h pad 2+2), dz 44.
// Flattened row n = ny*44 + wx. Output (h,w) base row = h*44 + w.
// Tap (kd,kh,kw): row offset kh*44 + kw in plane d+kd.
// xp[b][dz][n][ci], ci contiguous (128B rows).
// ===========================================================================
#define WPLANE 44
#define NPLANE 1984          // 44*44=1936 + overrun pad for staging
#define NVALID 1760          // 40*44
#define A_ROWS 436           // 256 + 4*44 + 4

__device__ __align__(128) __half g_xp[2ull * 44 * NPLANE * 64];
__device__ __align__(128) __half g_wh[125 * 144 * 64];   // [t][co][ci], t=(kd*5+kh)*5+kw

__device__ __forceinline__ float sus_f(float v) {
    return v > 0.f ? expf(-1.f / v) : 0.f;
}

// ===========================================================================
// Builder: writes g_wh[t][co][ci] fp16 directly. 0.1 conv scale folded,
// self-connection folded into center tap t=62.
// One thread per (t,u,w): 125*256 = 32000 threads.
// ===========================================================================
__global__ void build_weights_kernel(const float* __restrict__ wtp,
                                     const float* __restrict__ wsc0,
                                     const float* __restrict__ wsc1) {
    int id = blockIdx.x * blockDim.x + threadIdx.x;
    if (id >= 32000) return;
    int t  = id >> 8;
    int uw = id & 255;
    int u  = uw >> 4;
    int w  = uw & 15;

    int xi = t / 25, yi = (t / 5) % 5, zi = t % 5;
    float rx = -1.f + 0.5f * xi;
    float ry = -1.f + 0.5f * yi;
    float rz = -1.f + 0.5f * zi;
    float d  = sqrtf(rx * rx + ry * ry + rz * rz);

    const float EC = 1.14136f * expf(2.0f);
    float wv[7];
#pragma unroll
    for (int i = 0; i < 7; i++) wv[i] = 0.f;
#pragma unroll
    for (int r = 0; r < 5; r++) {
        float val  = (float)(r + 1) * (1.f / 6.f);
        float diff = (d - val) * 6.f;
        float e    = EC * sus_f(diff + 1.f) * sus_f(1.f - diff);
        if (e != 0.f) {
#pragma unroll
            for (int i = 0; i < 7; i++)
                wv[i] += e * wtp[r * 1792 + i * 256 + u * 16 + w];
        }
    }
    const float invS = 0.089442719099991587f;  // 1/5^1.5
#pragma unroll
    for (int i = 0; i < 7; i++) wv[i] *= invS;

    float n  = fmaxf(d, 1e-12f);
    float ux = rx / n, uy = ry / n, uz = rz / n;
    const float SQ3 = 1.7320508075688772f;
    const float SQ5 = 2.2360679774997896f;
    float sh1[3] = {SQ3 * ux, SQ3 * uy, SQ3 * uz};
    float sh2[5] = {SQ5 * SQ3 * ux * uz,
                    SQ5 * SQ3 * ux * uy,
                    SQ5 * (uy * uy - 0.5f * (ux * ux + uz * uz)),
                    SQ5 * SQ3 * uy * uz,
                    SQ5 * 0.5f * SQ3 * (uz * uz - ux * ux)};

    float C[3][3][5];
#pragma unroll
    for (int i = 0; i < 3; i++)
#pragma unroll
        for (int j = 0; j < 3; j++)
#pragma unroll
            for (int k = 0; k < 5; k++) C[i][j][k] = 0.f;
    {
        float s = sqrtf(2.f / 15.f);
        float h = 0.5f * sqrtf(3.f) * s;
        C[0][2][0] = h;  C[2][0][0] = h;
        C[0][1][1] = h;  C[1][0][1] = h;
        C[0][0][2] = -0.5f * s;  C[1][1][2] = s;  C[2][2][2] = -0.5f * s;
        C[1][2][3] = h;  C[2][1][3] = h;
        C[0][0][4] = -h; C[2][2][4] = h;
    }

    const float PW0 = 0.17677669529663687f;
    const float PW1 = 0.25f;
    const float PW2 = 0.39528470752104744f;
    const float F   = 0.1f;

    __half* wt = g_wh + (size_t)t * 144 * 64;
    // write W(co, ci)
#define WRW(co, ci, v) wt[(size_t)(co) * 64 + (ci)] = __float2half(v)

    {
        float v = F * PW0 * wv[0];
        if (t == 62) v += 0.25f * wsc0[u * 16 + w];
        WRW(w, u, v);
    }
#pragma unroll
    for (int k = 0; k < 3; k++)
        WRW(16 + 3 * w + k, u, F * (PW1 / SQ3) * sh1[k] * wv[1]);
#pragma unroll
    for (int k = 0; k < 5; k++)
        WRW(64 + 5 * w + k, u, F * (PW2 / SQ5) * sh2[k] * wv[2]);

#pragma unroll
    for (int i = 0; i < 3; i++) {
        int ci = 16 + 3 * u + i;
        WRW(w, ci, F * (PW0 / SQ3) * sh1[i] * wv[4]);
#pragma unroll
        for (int k = 0; k < 3; k++) {
            float t2 = 0.f;
#pragma unroll
            for (int j = 0; j < 5; j++) t2 += C[i][k][j] * sh2[j];
            float v = (i == k ? (PW1 / SQ3) * wv[3] : 0.f) + PW1 * t2 * wv[6];
            v *= F;
            if (t == 62 && i == k) v += 0.25f * wsc1[u * 16 + w];
            WRW(16 + 3 * w + k, ci, v);
        }
#pragma unroll
        for (int k = 0; k < 5; k++) {
            float t3 = 0.f;
#pragma unroll
            for (int j = 0; j < 3; j++) t3 += C[i][j][k] * sh1[j];
            WRW(64 + 5 * w + k, ci, F * PW2 * t3 * wv[5]);
        }
    }
#undef WRW
}

// ===========================================================================
__global__ void zero_xp_kernel() {
    size_t n4 = (2ull * 44 * NPLANE * 64 * 2) / 16;
    float4 z = make_float4(0.f, 0.f, 0.f, 0.f);
    float4* a = (float4*)g_xp;
    for (size_t i = blockIdx.x * blockDim.x + threadIdx.x; i < n4;
         i += (size_t)gridDim.x * blockDim.x)
        a[i] = z;
}

// grid (ny=44, dz=44, b=2), 256 threads: transpose ci innermost, fp32->fp16
__global__ void fill_xp_kernel(const float* __restrict__ x) {
    int ny = blockIdx.x, dz = blockIdx.y, b = blockIdx.z;
    if (dz < 2 || dz >= 42 || ny < 2 || ny >= 42) return;
    __shared__ float sm[40 * 65];
    int tid = threadIdx.x;
    int d = dz - 2, h = ny - 2;
    for (int i = tid; i < 64 * 40; i += 256) {
        int ci = i / 40, w = i % 40;
        sm[w * 65 + ci] = x[((size_t)(b * 64 + ci) * 40 + d) * 1600 + h * 40 + w];
    }
    __syncthreads();
    size_t rowbase = ((size_t)(b * 44 + dz) * NPLANE + ny * WPLANE) * 64;
    for (int j = tid; j < 40 * 64; j += 256) {
        int w = j / 64, ci = j % 64;
        g_xp[rowbase + (size_t)(w + 2) * 64 + ci] = __float2half(sm[w * 65 + ci]);
    }
}

// ===========================================================================
// Main conv: implicit GEMM on mma.sync (HMMA), fp16 single pass.
// Block: 256 voxels x 144 co, 8 warps (warp tile 64x72).
// A staged once per kd (kh,kw are row offsets), double buffered.
// B double buffered per tap. SMEM rows 144B stride (conflict-free ldmatrix).
// ===========================================================================
#define A_BYTES (A_ROWS * 144)             // 62784
#define B_BYTES (144 * 144)                // 20736
#define SM_A0   0
#define SM_A1   A_BYTES
#define SM_B0   (2 * A_BYTES)              // 125568
#define SM_B1   (SM_B0 + B_BYTES)          // 146304
#define SMEM_TOTAL (SM_B1 + B_BYTES)       // 167040

__device__ __forceinline__ uint32_t smem_u32(const void* p) {
    uint32_t a;
    asm("{ .reg .u64 t; cvta.to.shared.u64 t, %1; cvt.u32.u64 %0, t; }" : "=r"(a) : "l"(p));
    return a;
}
__device__ __forceinline__ void cpa16(uint32_t dst, const void* src) {
    asm volatile("cp.async.cg.shared.global [%0], [%1], 16;" :: "r"(dst), "l"(src));
}
__device__ __forceinline__ void cpa_commit() {
    asm volatile("cp.async.commit_group;" ::: "memory");
}
__device__ __forceinline__ void cpa_wait0() {
    asm volatile("cp.async.wait_group 0;" ::: "memory");
}
__device__ __forceinline__ void cpa_wait1() {
    asm volatile("cp.async.wait_group 1;" ::: "memory");
}
__device__ __forceinline__ void ldsm4(uint32_t* r, uint32_t addr) {
    asm volatile("ldmatrix.sync.aligned.m8n8.x4.shared.b16 {%0,%1,%2,%3}, [%4];"
                 : "=r"(r[0]), "=r"(r[1]), "=r"(r[2]), "=r"(r[3]) : "r"(addr));
}
__device__ __forceinline__ void ldsm2(uint32_t* r, uint32_t addr) {
    asm volatile("ldmatrix.sync.aligned.m8n8.x2.shared.b16 {%0,%1}, [%2];"
                 : "=r"(r[0]), "=r"(r[1]) : "r"(addr));
}
__device__ __forceinline__ void mma16816(float* d, const uint32_t* a, const uint32_t* bq) {
    asm volatile(
        "mma.sync.aligned.m16n8k16.row.col.f32.f16.f16.f32 "
        "{%0,%1,%2,%3}, {%4,%5,%6,%7}, {%8,%9}, {%0,%1,%2,%3};"
        : "+f"(d[0]), "+f"(d[1]), "+f"(d[2]), "+f"(d[3])
        : "r"(a[0]), "r"(a[1]), "r"(a[2]), "r"(a[3]), "r"(bq[0]), "r"(bq[1]));
}

__global__ void __launch_bounds__(256, 1)
conv_mma_kernel(float* __restrict__ out) {
    extern __shared__ char smem[];
    uint32_t sb = smem_u32(smem);
    const int tid  = threadIdx.x;
    const int lane = tid & 31;
    const int wid  = tid >> 5;
    const int mw   = wid & 3;     // M quarter (64 voxels)
    const int nw   = wid >> 2;    // N half (72 co)

    const int d = blockIdx.y;
    const int b = blockIdx.z;
    const int n0 = blockIdx.x * 256;    // 0..6 -> rows n0..n0+255

    // ---- staging ----
    auto stageA = [&](int kd, uint32_t base) {
        const __half* src0 = g_xp + ((size_t)(b * 44 + d + kd) * NPLANE + n0) * 64;
        for (int i = tid; i < A_ROWS * 8; i += 256) {
            int r = i >> 3, c = i & 7;
            cpa16(base + r * 144 + c * 16, src0 + (size_t)r * 64 + c * 8);
        }
    };
    auto stageB = [&](int t, uint32_t base) {
        const __half* src0 = g_wh + (size_t)t * 144 * 64;
        for (int i = tid; i < 144 * 8; i += 256) {
            int r = i >> 3, c = i & 7;
            cpa16(base + r * 144 + c * 16, src0 + (size_t)r * 64 + c * 8);
        }
    };

    stageA(0, sb + SM_A0);
    stageB(0, sb + SM_B0);
    cpa_commit();
    cpa_wait0();
    __syncthreads();

    float acc[4][9][4];
#pragma unroll
    for (int mt = 0; mt < 4; mt++)
#pragma unroll
        for (int nt = 0; nt < 9; nt++)
#pragma unroll
            for (int q = 0; q < 4; q++) acc[mt][nt][q] = 0.f;

    // lane-dependent base offsets
    const uint32_t aLaneOff = (uint32_t)((mw * 64 + (lane & 15)) * 144 + (lane >> 4) * 16);
    const uint32_t bOff4 = (uint32_t)((nw * 72 + ((lane >> 4) << 3) + (lane & 7)) * 144 +
                                      ((lane >> 3) & 1) * 16);
    const uint32_t bOff2 = (uint32_t)((nw * 72 + 64 + (lane & 7)) * 144 +
                                      ((lane >> 3) & 1) * 16);

    uint32_t aCur = sb + SM_A0, aNxt = sb + SM_A1;

    for (int kd = 0; kd < 5; kd++) {
        for (int j = 0; j < 25; j++) {
            int t = kd * 25 + j;
            bool prefA = (j == 0) && (kd < 4);
            if (t < 124) {
                stageB(t + 1, sb + (((t + 1) & 1) ? SM_B1 : SM_B0));
                cpa_commit();
            }
            if (prefA) {
                stageA(kd + 1, aNxt);
                cpa_commit();
            }

            int kh = j / 5, kw = j % 5;
            uint32_t aTap  = aCur + aLaneOff + (uint32_t)((kh * WPLANE + kw) * 144);
            uint32_t bBase = sb + ((t & 1) ? SM_B1 : SM_B0);

#pragma unroll 1
            for (int ks = 0; ks < 4; ks++) {
                uint32_t a[4][4];
#pragma unroll
                for (int mt = 0; mt < 4; mt++)
                    ldsm4(a[mt], aTap + mt * (16 * 144) + ks * 32);

                uint32_t bf[9][2];
#pragma unroll
                for (int nt = 0; nt < 4; nt++) {
                    uint32_t r4[4];
                    ldsm4(r4, bBase + bOff4 + nt * (16 * 144) + ks * 32);
                    bf[2 * nt][0] = r4[0]; bf[2 * nt][1] = r4[1];
                    bf[2 * nt + 1][0] = r4[2]; bf[2 * nt + 1][1] = r4[3];
                }
                ldsm2(bf[8], bBase + bOff2 + ks * 32);

#pragma unroll
                for (int mt = 0; mt < 4; mt++)
#pragma unroll
                    for (int nt = 0; nt < 9; nt++)
                        mma16816(acc[mt][nt], a[mt], bf[nt]);
            }

            if (prefA) cpa_wait1();   // drain B(t+1), leave A(kd+1) in flight
            else       cpa_wait0();
            __syncthreads();
        }
        { uint32_t tmp = aCur; aCur = aNxt; aNxt = tmp; }
    }

    // ---- epilogue ----
    const size_t ob = (size_t)b * 144 * 64000 + (size_t)d * 1600;
#pragma unroll
    for (int mt = 0; mt < 4; mt++) {
        int v0 = n0 + mw * 64 + mt * 16 + (lane >> 2);
        int v1 = v0 + 8;
        int h0 = v0 / WPLANE, w0 = v0 % WPLANE;
        int h1 = v1 / WPLANE, w1 = v1 % WPLANE;
        bool ok0 = (w0 < 40) && (v0 < NVALID);
        bool ok1 = (w1 < 40) && (v1 < NVALID);
        size_t o0 = ob + h0 * 40 + w0;
        size_t o1 = ob + h1 * 40 + w1;
#pragma unroll
        for (int nt = 0; nt < 9; nt++) {
            int co = nw * 72 + nt * 8 + (lane & 3) * 2;
            if (ok0) {
                out[o0 + (size_t)co * 64000]       = acc[mt][nt][0];
                out[o0 + (size_t)(co + 1) * 64000] = acc[mt][nt][1];
            }
            if (ok1) {
                out[o1 + (size_t)co * 64000]       = acc[mt][nt][2];
                out[o1 + (size_t)(co + 1) * 64000] = acc[mt][nt][3];
            }
        }
    }
}

// ===========================================================================
extern "C" void kernel_launch(void* const* d_in, const int* in_sizes, int n_in,
                              void* d_out, int out_size) {
    const float* x    = (const float*)d_in[0];
    const float* wsc0 = (const float*)d_in[1];
    const float* wsc1 = (const float*)d_in[2];
    const float* wtp  = (const float*)d_in[3];
    float* out = (float*)d_out;

    zero_xp_kernel<<<2048, 256>>>();
    fill_xp_kernel<<<dim3(44, 44, 2), 256>>>(x);
    build_weights_kernel<<<125, 256>>>(wtp, wsc0, wsc1);

    cudaFuncSetAttribute(conv_mma_kernel,
                         cudaFuncAttributeMaxDynamicSharedMemorySize, SMEM_TOTAL);
    conv_mma_kernel<<<dim3(7, 40, 2), 256, SMEM_TOTAL>>>(out);
}